// round 1
// baseline (speedup 1.0000x reference)
#include <cuda_runtime.h>
#include <math.h>

// Problem constants
#define BB 2048
#define DD 4096
#define PP 64
#define EE 8
#define CC 64
#define KK 64
#define TWO_C 128

// smem layout (padded odd strides -> conflict-free LDS)
#define XS_STRIDE 65          // x tile [P=64][65]
#define WS_STRIDE 65          // w tile [2C=128][65]
#define SMEM_FLOATS (PP * XS_STRIDE + TWO_C * WS_STRIDE)

// scratch for the deterministic loss reduction (device globals: allowed)
__device__ float g_select[BB * EE];
__device__ int   g_index[BB];

// ---------------------------------------------------------------------------
// Fused kernel: one block per batch element b, 256 threads.
//   1) load x[b] (4096 f32) to smem
//   2) router: xs[k] = sum_p x[p,k]; select[e] = xs . rw[e]; gate/argmax
//   3) write select0 one-hot row, stash select/index for loss kernel
//   4) expert GEMM a[c,p] (128x64x64) for the selected expert only
//   5) epilogue: sum (a + bias_c)^3 over p and over the two c-halves,
//      out[b] = softmax(gate * v)
// ---------------------------------------------------------------------------
__global__ __launch_bounds__(256) void moe_fused(
    const float* __restrict__ x,
    const float* __restrict__ rw,
    const float* __restrict__ ew,
    const float* __restrict__ eb,
    float* __restrict__ out,
    int write_aux)
{
    extern __shared__ float sm[];
    float* xsm = sm;                       // [64][XS_STRIDE]
    float* wsm = sm + PP * XS_STRIDE;      // [128][WS_STRIDE]

    __shared__ float xs[KK];
    __shared__ float sel[EE];
    __shared__ float bsm[TWO_C];
    __shared__ float wred[8];
    __shared__ int   s_idx;
    __shared__ float s_gate;

    const int b = blockIdx.x;
    const int t = threadIdx.x;
    const float* xb = x + (size_t)b * DD;

    // ---- load x[b] into padded smem [p][k] (coalesced gmem, conflict-free STS)
    for (int d = t; d < DD; d += 256) {
        int p = d >> 6, k = d & 63;
        xsm[p * XS_STRIDE + k] = xb[d];
    }
    __syncthreads();

    // ---- xs[k] = sum_p x[p][k]
    if (t < KK) {
        float s = 0.f;
        #pragma unroll
        for (int p = 0; p < PP; p++) s += xsm[p * XS_STRIDE + t];
        xs[t] = s;
    }
    __syncthreads();

    // ---- router logits
    if (t < EE) {
        float s = 0.f;
        const float* r = rw + t * KK;
        #pragma unroll
        for (int k = 0; k < KK; k++) s += xs[k] * r[k];
        sel[t] = s;
        g_select[b * EE + t] = s;
    }
    __syncthreads();

    if (t == 0) {
        float g = sel[0]; int idx = 0;
        #pragma unroll
        for (int e = 1; e < EE; e++) {
            float v = sel[e];
            if (v > g) { g = v; idx = e; }   // strict '>' keeps first on ties (matches argmax)
        }
        s_idx = idx; s_gate = g;
        g_index[b] = idx;
    }
    __syncthreads();

    const int   eidx = s_idx;
    const float gate = s_gate;

    // ---- select0 one-hot row: dispatch = (gate*onehot != 0)
    if (write_aux && t < EE) {
        out[BB * 2 + b * EE + t] = (t == eidx && gate != 0.f) ? 1.f : 0.f;
    }

    // ---- stage selected expert's weights + bias in smem
    const float* we = ew + (size_t)eidx * (TWO_C * KK);
    for (int i = t; i < TWO_C * KK; i += 256) {
        int c = i >> 6, k = i & 63;
        wsm[c * WS_STRIDE + k] = we[i];
    }
    if (t < TWO_C) bsm[t] = eb[eidx * TWO_C + t];
    __syncthreads();

    // ---- GEMM: thread tile 4c x 8p; c = 4*ci + i (contiguous), p = pi + 8*j
    const int pi = t & 7;        // 0..7
    const int ci = t >> 3;       // 0..31  (warp w covers ci 4w..4w+3 -> one c-half per warp)

    float acc[4][8];
    #pragma unroll
    for (int i = 0; i < 4; i++)
        #pragma unroll
        for (int j = 0; j < 8; j++) acc[i][j] = 0.f;

    const float* wp = wsm + (ci * 4) * WS_STRIDE;

    #pragma unroll 8
    for (int k = 0; k < KK; k++) {
        float wv0 = wp[0 * WS_STRIDE + k];
        float wv1 = wp[1 * WS_STRIDE + k];
        float wv2 = wp[2 * WS_STRIDE + k];
        float wv3 = wp[3 * WS_STRIDE + k];
        #pragma unroll
        for (int j = 0; j < 8; j++) {
            float xv = xsm[(pi + 8 * j) * XS_STRIDE + k];
            acc[0][j] += wv0 * xv;
            acc[1][j] += wv1 * xv;
            acc[2][j] += wv2 * xv;
            acc[3][j] += wv3 * xv;
        }
    }

    // ---- epilogue: cube with bias, partial sum (all 4 c's of a thread share a half)
    float part = 0.f;
    #pragma unroll
    for (int i = 0; i < 4; i++) {
        float bbv = bsm[ci * 4 + i];
        #pragma unroll
        for (int j = 0; j < 8; j++) {
            float z = acc[i][j] + bbv;
            part += z * z * z;
        }
    }
    #pragma unroll
    for (int o = 16; o > 0; o >>= 1)
        part += __shfl_xor_sync(0xffffffffu, part, o);
    const int warp = t >> 5;
    if ((t & 31) == 0) wred[warp] = part;
    __syncthreads();

    if (t == 0) {
        float v0 = wred[0] + wred[1] + wred[2] + wred[3];   // c in [0,64)
        float v1 = wred[4] + wred[5] + wred[6] + wred[7];   // c in [64,128)
        float a0 = gate * v0, a1 = gate * v1;
        float m  = fmaxf(a0, a1);
        float e0 = expf(a0 - m), e1 = expf(a1 - m);
        float inv = 1.f / (e0 + e1);
        out[b * 2 + 0] = e0 * inv;
        out[b * 2 + 1] = e1 * inv;
    }
}

// ---------------------------------------------------------------------------
// Deterministic loss reduction:
//   loss = E * sum_e ( (sum_b select[b,e]) * count[e] ) / B^2
// ---------------------------------------------------------------------------
__global__ __launch_bounds__(256) void loss_kernel(float* __restrict__ out_loss)
{
    __shared__ float psum[256];
    __shared__ int   pcnt[256];

    float my[EE];
    int   myc[EE];
    #pragma unroll
    for (int e = 0; e < EE; e++) { my[e] = 0.f; myc[e] = 0; }

    for (int b = threadIdx.x; b < BB; b += 256) {
        const int idx = g_index[b];
        #pragma unroll
        for (int e = 0; e < EE; e++) my[e] += g_select[b * EE + e];
        myc[idx]++;
    }

    float loss = 0.f;
    for (int e = 0; e < EE; e++) {
        psum[threadIdx.x] = my[e];
        pcnt[threadIdx.x] = myc[e];
        __syncthreads();
        for (int s = 128; s > 0; s >>= 1) {
            if (threadIdx.x < s) {
                psum[threadIdx.x] += psum[threadIdx.x + s];
                pcnt[threadIdx.x] += pcnt[threadIdx.x + s];
            }
            __syncthreads();
        }
        if (threadIdx.x == 0) loss += psum[0] * (float)pcnt[0];
        __syncthreads();
    }
    if (threadIdx.x == 0)
        out_loss[0] = loss * (float)EE / ((float)BB * (float)BB);
}

// ---------------------------------------------------------------------------
extern "C" void kernel_launch(void* const* d_in, const int* in_sizes, int n_in,
                              void* d_out, int out_size)
{
    const float* x  = (const float*)d_in[0];
    const float* rw = (const float*)d_in[1];
    const float* ew = (const float*)d_in[2];
    const float* eb = (const float*)d_in[3];
    float* out = (float*)d_out;

    const int full = (out_size >= BB * 2 + BB * EE + 1) ? 1 : 0;

    const size_t smem = SMEM_FLOATS * sizeof(float);   // ~49.9 KB -> needs opt-in
    cudaFuncSetAttribute(moe_fused, cudaFuncAttributeMaxDynamicSharedMemorySize, (int)smem);

    moe_fused<<<BB, 256, smem>>>(x, rw, ew, eb, out, full);
    if (full) {
        loss_kernel<<<1, 256>>>(out + BB * 2 + BB * EE);
    }
}

// round 3
// speedup vs baseline: 2.6649x; 2.6649x over previous
#include <cuda_runtime.h>
#include <cuda_bf16.h>
#include <cstdint>
#include <math.h>

// Problem constants
#define BB 2048
#define DD 4096
#define PP 64
#define EE 8
#define KK 64
#define TWO_C 128

#define WROW 88          // padded row stride in bf16 (176 B): conflict-free ldmatrix
#define WROWB 176

// scratch
__device__ float g_select[BB * EE];
__device__ int   g_index[BB];
__device__ __align__(16) __nv_bfloat16 g_wbf[EE * TWO_C * WROW];  // padded bf16 weights

// ---------------- helpers ----------------
__device__ __forceinline__ uint32_t smem_u32(const void* p) {
    uint32_t a;
    asm("{ .reg .u64 t; cvta.to.shared.u64 t, %1; cvt.u32.u64 %0, t; }" : "=r"(a) : "l"(p));
    return a;
}

__device__ __forceinline__ void ldsm_x4(uint32_t& r0, uint32_t& r1, uint32_t& r2, uint32_t& r3,
                                        uint32_t addr) {
    asm volatile("ldmatrix.sync.aligned.m8n8.x4.shared.b16 {%0,%1,%2,%3}, [%4];"
                 : "=r"(r0), "=r"(r1), "=r"(r2), "=r"(r3) : "r"(addr));
}

__device__ __forceinline__ void mma_bf16(float* d, const uint32_t* a, uint32_t b0, uint32_t b1) {
    asm volatile(
        "mma.sync.aligned.m16n8k16.row.col.f32.bf16.bf16.f32 "
        "{%0,%1,%2,%3}, {%4,%5,%6,%7}, {%8,%9}, {%0,%1,%2,%3};"
        : "+f"(d[0]), "+f"(d[1]), "+f"(d[2]), "+f"(d[3])
        : "r"(a[0]), "r"(a[1]), "r"(a[2]), "r"(a[3]), "r"(b0), "r"(b1));
}

// ---------------------------------------------------------------------------
// Weight prep: fp32 [E][128][64] -> bf16 padded [E][128][88]
// ---------------------------------------------------------------------------
__global__ __launch_bounds__(1024) void prep_weights(const float* __restrict__ ew)
{
    int idx = blockIdx.x * 1024 + threadIdx.x;           // 0 .. 65535
    int e = idx >> 13;
    int rem = idx & 8191;
    int c = rem >> 6, k = rem & 63;
    g_wbf[e * (TWO_C * WROW) + c * WROW + k] = __float2bfloat16(ew[idx]);
}

// ---------------------------------------------------------------------------
// Fused kernel: one block per batch element, 256 threads (8 warps).
// Router exact fp32; expert GEMM via mma.sync bf16; cube epilogue fp32.
// ---------------------------------------------------------------------------
__global__ __launch_bounds__(256) void moe_fused(
    const float* __restrict__ x,
    const float* __restrict__ rw,
    const float* __restrict__ eb,
    float* __restrict__ out,
    int write_aux)
{
    __shared__ __align__(16) __nv_bfloat16 asm_w[TWO_C * WROW];  // A: weights [c][k]
    __shared__ __align__(16) __nv_bfloat16 bsm_x[PP * WROW];     // B: x patches [p][k]
    __shared__ float xpart[256];
    __shared__ float xs[KK];
    __shared__ float sel[EE];
    __shared__ float bias_s[TWO_C];
    __shared__ float wred[8];
    __shared__ int   s_idx;
    __shared__ float s_gate;

    const int b = blockIdx.x;
    const int t = threadIdx.x;
    const int wid = t >> 5, lid = t & 31;
    const float* xb = x + (size_t)b * DD;

    // ---- load x[b]: fp32 partial sums (router) + bf16 B tile [p][k], stride 88
    {
        float acc = 0.f;
        const int k = t & 63;
        #pragma unroll
        for (int i = 0; i < 16; i++) {
            int d = t + (i << 8);
            float v = xb[d];
            acc += v;
            int p = (t >> 6) + (i << 2);
            bsm_x[p * WROW + k] = __float2bfloat16(v);
        }
        xpart[t] = acc;
    }
    __syncthreads();

    if (t < KK) xs[t] = xpart[t] + xpart[t + 64] + xpart[t + 128] + xpart[t + 192];
    __syncthreads();

    if (t < EE) {
        float s = 0.f;
        const float* r = rw + t * KK;
        #pragma unroll
        for (int k = 0; k < KK; k++) s += xs[k] * r[k];
        sel[t] = s;
        g_select[b * EE + t] = s;
    }
    __syncthreads();

    if (t == 0) {
        float g = sel[0]; int idx = 0;
        #pragma unroll
        for (int e = 1; e < EE; e++) { float v = sel[e]; if (v > g) { g = v; idx = e; } }
        s_idx = idx; s_gate = g; g_index[b] = idx;
    }
    __syncthreads();

    const int   eidx = s_idx;
    const float gate = s_gate;

    if (write_aux && t < EE)
        out[BB * 2 + b * EE + t] = (t == eidx && gate != 0.f) ? 1.f : 0.f;

    // ---- stage selected expert's bf16 weights (vectorized 16B copies) + bias
    {
        const uint4* src = (const uint4*)(g_wbf + (size_t)eidx * (TWO_C * WROW));
        uint4* dst = (uint4*)asm_w;
        // 128 rows x 8 uint4 per row (first 64 bf16 = 128B of each 176B row)
        #pragma unroll
        for (int j = 0; j < 4; j++) {
            int i = t + (j << 8);            // 0..1023
            int row = i >> 3, q = i & 7;
            dst[row * 11 + q] = src[row * 11 + q];
        }
    }
    if (t < TWO_C) bias_s[t] = eb[eidx * TWO_C + t];
    __syncthreads();

    // ---- GEMM: warp wid owns c rows [16*wid, 16*wid+16), all 64 p
    const uint32_t Abase = smem_u32(asm_w);
    const uint32_t Bbase = smem_u32(bsm_x);
    const int c0 = wid << 4;

    // ldmatrix lane addresses
    const uint32_t a_addr = Abase + (uint32_t)((c0 + (lid & 15)) * WROWB + ((lid >> 4) << 4));
    const uint32_t b_addr = Bbase + (uint32_t)(((lid & 7) + ((lid >> 4) << 3)) * WROWB
                                               + (((lid >> 3) & 1) << 4));

    float acc[8][4];
    #pragma unroll
    for (int n = 0; n < 8; n++)
        #pragma unroll
        for (int i = 0; i < 4; i++) acc[n][i] = 0.f;

    #pragma unroll
    for (int ks = 0; ks < 4; ks++) {
        uint32_t a[4];
        ldsm_x4(a[0], a[1], a[2], a[3], a_addr + ks * 32);
        #pragma unroll
        for (int j = 0; j < 4; j++) {
            uint32_t r0, r1, r2, r3;
            ldsm_x4(r0, r1, r2, r3, b_addr + j * (16 * WROWB) + ks * 32);
            mma_bf16(acc[2 * j],     a, r0, r1);
            mma_bf16(acc[2 * j + 1], a, r2, r3);
        }
    }

    // ---- epilogue: z = d + bias[c]; sum z^3 over p; c1 = c0+(lid>>2), c2 = c1+8
    const float bv1 = bias_s[c0 + (lid >> 2)];
    const float bv2 = bias_s[c0 + (lid >> 2) + 8];
    float part = 0.f;
    #pragma unroll
    for (int n = 0; n < 8; n++) {
        float z0 = acc[n][0] + bv1;
        float z1 = acc[n][1] + bv1;
        float z2 = acc[n][2] + bv2;
        float z3 = acc[n][3] + bv2;
        part += z0 * z0 * z0 + z1 * z1 * z1 + z2 * z2 * z2 + z3 * z3 * z3;
    }
    #pragma unroll
    for (int o = 16; o > 0; o >>= 1)
        part += __shfl_xor_sync(0xffffffffu, part, o);
    if (lid == 0) wred[wid] = part;
    __syncthreads();

    if (t == 0) {
        float v0 = wred[0] + wred[1] + wred[2] + wred[3];   // c in [0,64)
        float v1 = wred[4] + wred[5] + wred[6] + wred[7];   // c in [64,128)
        float a0 = gate * v0, a1 = gate * v1;
        float m  = fmaxf(a0, a1);
        float e0 = expf(a0 - m), e1 = expf(a1 - m);
        float inv = 1.f / (e0 + e1);
        out[b * 2 + 0] = e0 * inv;
        out[b * 2 + 1] = e1 * inv;
    }
}

// ---------------------------------------------------------------------------
// loss = E/B^2 * sum_e (sum_b select[b,e]) * count[e]   (deterministic)
// ---------------------------------------------------------------------------
__global__ __launch_bounds__(1024) void loss_kernel(float* __restrict__ out_loss)
{
    const int t = threadIdx.x;
    float my[EE];
    int   cnt[EE];
    #pragma unroll
    for (int e = 0; e < EE; e++) { my[e] = 0.f; cnt[e] = 0; }

    for (int b = t; b < BB; b += 1024) {
        const float4* r = (const float4*)(g_select + b * EE);
        float4 v0 = r[0], v1 = r[1];
        my[0] += v0.x; my[1] += v0.y; my[2] += v0.z; my[3] += v0.w;
        my[4] += v1.x; my[5] += v1.y; my[6] += v1.z; my[7] += v1.w;
        int idx = g_index[b];
        #pragma unroll
        for (int e = 0; e < EE; e++) cnt[e] += (idx == e);
    }

    #pragma unroll
    for (int o = 16; o > 0; o >>= 1) {
        #pragma unroll
        for (int e = 0; e < EE; e++) {
            my[e]  += __shfl_xor_sync(0xffffffffu, my[e], o);
            cnt[e] += __shfl_xor_sync(0xffffffffu, cnt[e], o);
        }
    }

    __shared__ float ws[32][EE];
    __shared__ int   wc[32][EE];
    __shared__ float ps[EE];
    const int wid = t >> 5, lid = t & 31;
    if (lid == 0) {
        #pragma unroll
        for (int e = 0; e < EE; e++) { ws[wid][e] = my[e]; wc[wid][e] = cnt[e]; }
    }
    __syncthreads();

    if (t < EE) {
        float S = 0.f; int C = 0;
        #pragma unroll
        for (int w = 0; w < 32; w++) { S += ws[w][t]; C += wc[w][t]; }
        ps[t] = S * (float)C;
    }
    __syncthreads();

    if (t == 0) {
        float L = 0.f;
        #pragma unroll
        for (int e = 0; e < EE; e++) L += ps[e];
        out_loss[0] = L * (float)EE / ((float)BB * (float)BB);
    }
}

// ---------------------------------------------------------------------------
extern "C" void kernel_launch(void* const* d_in, const int* in_sizes, int n_in,
                              void* d_out, int out_size)
{
    const float* x  = (const float*)d_in[0];
    const float* rw = (const float*)d_in[1];
    const float* ew = (const float*)d_in[2];
    const float* eb = (const float*)d_in[3];
    float* out = (float*)d_out;

    const int full = (out_size >= BB * 2 + BB * EE + 1) ? 1 : 0;

    prep_weights<<<64, 1024>>>(ew);
    moe_fused<<<BB, 256>>>(x, rw, eb, out, full);
    if (full) {
        loss_kernel<<<1, 1024>>>(out + BB * 2 + BB * EE);
    }
}

// round 4
// speedup vs baseline: 2.8880x; 1.0837x over previous
#include <cuda_runtime.h>
#include <cuda_bf16.h>
#include <cstdint>
#include <math.h>

// Problem constants
#define BB 2048
#define DD 4096
#define PP 64
#define EE 8
#define KK 64
#define TWO_C 128

#define WROW 72          // padded row stride in bf16 (144 B): conflict-free ldmatrix
#define WROWB 144

// scratch
__device__ float g_select[BB * EE];
__device__ int   g_index[BB];
__device__ __align__(16) __nv_bfloat16 g_wbf[EE * TWO_C * WROW];  // padded bf16 weights

// ---------------- helpers ----------------
__device__ __forceinline__ uint32_t smem_u32(const void* p) {
    uint32_t a;
    asm("{ .reg .u64 t; cvta.to.shared.u64 t, %1; cvt.u32.u64 %0, t; }" : "=r"(a) : "l"(p));
    return a;
}

__device__ __forceinline__ void ldsm_x4(uint32_t& r0, uint32_t& r1, uint32_t& r2, uint32_t& r3,
                                        uint32_t addr) {
    asm volatile("ldmatrix.sync.aligned.m8n8.x4.shared.b16 {%0,%1,%2,%3}, [%4];"
                 : "=r"(r0), "=r"(r1), "=r"(r2), "=r"(r3) : "r"(addr));
}

__device__ __forceinline__ void mma_bf16(float* d, const uint32_t* a, uint32_t b0, uint32_t b1) {
    asm volatile(
        "mma.sync.aligned.m16n8k16.row.col.f32.bf16.bf16.f32 "
        "{%0,%1,%2,%3}, {%4,%5,%6,%7}, {%8,%9}, {%0,%1,%2,%3};"
        : "+f"(d[0]), "+f"(d[1]), "+f"(d[2]), "+f"(d[3])
        : "r"(a[0]), "r"(a[1]), "r"(a[2]), "r"(a[3]), "r"(b0), "r"(b1));
}

// ---------------------------------------------------------------------------
// Weight prep: fp32 [E][128][64] -> bf16 padded [E][128][72]
// 8192 threads, 8 consecutive k per thread (float4 x2 in, uint4 out)
// ---------------------------------------------------------------------------
__global__ __launch_bounds__(1024) void prep_weights(const float* __restrict__ ew)
{
    int idx = blockIdx.x * 1024 + threadIdx.x;   // [0, 8192)
    int row = idx >> 3;                           // e*128+c, [0,1024)
    int ch  = idx & 7;                            // k chunk of 8
    const float4* src = (const float4*)(ew + (size_t)row * 64 + ch * 8);
    float4 v0 = src[0], v1 = src[1];
    __nv_bfloat16 h[8];
    h[0] = __float2bfloat16(v0.x); h[1] = __float2bfloat16(v0.y);
    h[2] = __float2bfloat16(v0.z); h[3] = __float2bfloat16(v0.w);
    h[4] = __float2bfloat16(v1.x); h[5] = __float2bfloat16(v1.y);
    h[6] = __float2bfloat16(v1.z); h[7] = __float2bfloat16(v1.w);
    *(uint4*)(g_wbf + (size_t)row * WROW + ch * 8) = *(uint4*)h;
}

// ---------------------------------------------------------------------------
// Fused kernel: one block per batch element, 256 threads (8 warps).
// Router exact fp32; expert GEMM via mma.sync bf16 (warp tile 32c x 32p).
// ---------------------------------------------------------------------------
__global__ __launch_bounds__(256) void moe_fused(
    const float* __restrict__ x,
    const float* __restrict__ rw,
    const float* __restrict__ eb,
    float* __restrict__ out,
    int write_aux)
{
    __shared__ __align__(16) __nv_bfloat16 asm_w[TWO_C * WROW];  // A: weights [c][k]
    __shared__ __align__(16) __nv_bfloat16 bsm_x[PP * WROW];     // B: x patches [p][k]
    __shared__ float xpart[256];
    __shared__ float xs[KK];
    __shared__ float sel[EE];
    __shared__ float bias_s[TWO_C];
    __shared__ float wred[8];
    __shared__ int   s_idx;
    __shared__ float s_gate;

    const int b = blockIdx.x;
    const int t = threadIdx.x;
    const int wid = t >> 5, lid = t & 31;
    const float* xb = x + (size_t)b * DD;

    // ---- load x[b]: fp32 partial sums (router) + bf16 B tile [p][k]
    {
        float acc = 0.f;
        const int k = t & 63;
        #pragma unroll
        for (int i = 0; i < 16; i++) {
            int d = t + (i << 8);
            float v = xb[d];
            acc += v;
            int p = (t >> 6) + (i << 2);
            bsm_x[p * WROW + k] = __float2bfloat16(v);
        }
        xpart[t] = acc;
    }
    __syncthreads();

    if (t < KK) xs[t] = xpart[t] + xpart[t + 64] + xpart[t + 128] + xpart[t + 192];
    __syncthreads();

    if (t < EE) {
        float s = 0.f;
        const float* r = rw + t * KK;
        #pragma unroll
        for (int k = 0; k < KK; k++) s += xs[k] * r[k];
        sel[t] = s;
        g_select[b * EE + t] = s;
    }
    __syncthreads();

    if (t == 0) {
        float g = sel[0]; int idx = 0;
        #pragma unroll
        for (int e = 1; e < EE; e++) { float v = sel[e]; if (v > g) { g = v; idx = e; } }
        s_idx = idx; s_gate = g; g_index[b] = idx;
    }
    __syncthreads();

    const int   eidx = s_idx;
    const float gate = s_gate;

    if (write_aux && t < EE)
        out[BB * 2 + b * EE + t] = (t == eidx && gate != 0.f) ? 1.f : 0.f;

    // ---- stage selected expert's bf16 weights (16B copies, same padded layout)
    {
        const uint4* src = (const uint4*)(g_wbf + (size_t)eidx * (TWO_C * WROW));
        uint4* dst = (uint4*)asm_w;
        // 128 rows x 8 uint4 of payload per row (row = 9 uint4 incl. pad)
        #pragma unroll
        for (int j = 0; j < 4; j++) {
            int i = t + (j << 8);            // 0..1023
            int row = i >> 3, q = i & 7;
            dst[row * 9 + q] = src[row * 9 + q];
        }
    }
    if (t < TWO_C) bias_s[t] = eb[eidx * TWO_C + t];
    __syncthreads();

    // ---- GEMM: warp grid 4c x 2p; warp tile 32c x 32p
    const int cw = wid & 3;        // c-group
    const int pw = wid >> 2;       // p-group
    const uint32_t Abase = smem_u32(asm_w);
    const uint32_t Bbase = smem_u32(bsm_x);

    const uint32_t a_addr = Abase + (uint32_t)(((cw << 5) + (lid & 15)) * WROWB + ((lid >> 4) << 4));
    const uint32_t b_addr = Bbase + (uint32_t)(((pw << 5) + (lid & 7) + ((lid >> 4) << 3)) * WROWB
                                               + (((lid >> 3) & 1) << 4));

    float acc[2][4];
    #pragma unroll
    for (int m = 0; m < 2; m++)
        #pragma unroll
        for (int n = 0; n < 4; n++) { acc[m][n] = 0.f; }
    float accv[2][4][4];
    #pragma unroll
    for (int m = 0; m < 2; m++)
        #pragma unroll
        for (int n = 0; n < 4; n++)
            #pragma unroll
            for (int i = 0; i < 4; i++) accv[m][n][i] = 0.f;

    #pragma unroll
    for (int ks = 0; ks < 4; ks++) {
        uint32_t a0[4], a1[4];
        ldsm_x4(a0[0], a0[1], a0[2], a0[3], a_addr + ks * 32);
        ldsm_x4(a1[0], a1[1], a1[2], a1[3], a_addr + 16 * WROWB + ks * 32);
        #pragma unroll
        for (int j = 0; j < 2; j++) {
            uint32_t r0, r1, r2, r3;
            ldsm_x4(r0, r1, r2, r3, b_addr + j * (16 * WROWB) + ks * 32);
            mma_bf16(accv[0][2 * j],     a0, r0, r1);
            mma_bf16(accv[0][2 * j + 1], a0, r2, r3);
            mma_bf16(accv[1][2 * j],     a1, r0, r1);
            mma_bf16(accv[1][2 * j + 1], a1, r2, r3);
        }
    }

    // ---- epilogue: z = d + bias[c]; sum z^3 over all p of this warp
    float part = 0.f;
    #pragma unroll
    for (int m = 0; m < 2; m++) {
        const float bv1 = bias_s[(cw << 5) + (m << 4) + (lid >> 2)];
        const float bv2 = bias_s[(cw << 5) + (m << 4) + (lid >> 2) + 8];
        #pragma unroll
        for (int n = 0; n < 4; n++) {
            float z0 = accv[m][n][0] + bv1;
            float z1 = accv[m][n][1] + bv1;
            float z2 = accv[m][n][2] + bv2;
            float z3 = accv[m][n][3] + bv2;
            part += z0 * z0 * z0 + z1 * z1 * z1 + z2 * z2 * z2 + z3 * z3 * z3;
        }
    }
    #pragma unroll
    for (int o = 16; o > 0; o >>= 1)
        part += __shfl_xor_sync(0xffffffffu, part, o);
    if (lid == 0) wred[wid] = part;
    __syncthreads();

    if (t == 0) {
        // cw in {0,1} -> c<64 : warps 0,1,4,5 ; cw in {2,3} -> c>=64 : warps 2,3,6,7
        float v0 = wred[0] + wred[1] + wred[4] + wred[5];
        float v1 = wred[2] + wred[3] + wred[6] + wred[7];
        float a0 = gate * v0, a1 = gate * v1;
        float m  = fmaxf(a0, a1);
        float e0 = expf(a0 - m), e1 = expf(a1 - m);
        float inv = 1.f / (e0 + e1);
        out[b * 2 + 0] = e0 * inv;
        out[b * 2 + 1] = e1 * inv;
    }
}

// ---------------------------------------------------------------------------
// loss = E/B^2 * sum_e (sum_b select[b,e]) * count[e]   (deterministic)
// ---------------------------------------------------------------------------
__global__ __launch_bounds__(1024) void loss_kernel(float* __restrict__ out_loss)
{
    const int t = threadIdx.x;
    float my[EE];
    int   cnt[EE];
    #pragma unroll
    for (int e = 0; e < EE; e++) { my[e] = 0.f; cnt[e] = 0; }

    for (int b = t; b < BB; b += 1024) {
        const float4* r = (const float4*)(g_select + b * EE);
        float4 v0 = r[0], v1 = r[1];
        my[0] += v0.x; my[1] += v0.y; my[2] += v0.z; my[3] += v0.w;
        my[4] += v1.x; my[5] += v1.y; my[6] += v1.z; my[7] += v1.w;
        int idx = g_index[b];
        #pragma unroll
        for (int e = 0; e < EE; e++) cnt[e] += (idx == e);
    }

    #pragma unroll
    for (int o = 16; o > 0; o >>= 1) {
        #pragma unroll
        for (int e = 0; e < EE; e++) {
            my[e]  += __shfl_xor_sync(0xffffffffu, my[e], o);
            cnt[e] += __shfl_xor_sync(0xffffffffu, cnt[e], o);
        }
    }

    __shared__ float ws[32][EE];
    __shared__ int   wc[32][EE];
    __shared__ float ps[EE];
    const int wid = t >> 5, lid = t & 31;
    if (lid == 0) {
        #pragma unroll
        for (int e = 0; e < EE; e++) { ws[wid][e] = my[e]; wc[wid][e] = cnt[e]; }
    }
    __syncthreads();

    if (t < EE) {
        float S = 0.f; int C = 0;
        #pragma unroll
        for (int w = 0; w < 32; w++) { S += ws[w][t]; C += wc[w][t]; }
        ps[t] = S * (float)C;
    }
    __syncthreads();

    if (t == 0) {
        float L = 0.f;
        #pragma unroll
        for (int e = 0; e < EE; e++) L += ps[e];
        out_loss[0] = L * (float)EE / ((float)BB * (float)BB);
    }
}

// ---------------------------------------------------------------------------
extern "C" void kernel_launch(void* const* d_in, const int* in_sizes, int n_in,
                              void* d_out, int out_size)
{
    const float* x  = (const float*)d_in[0];
    const float* rw = (const float*)d_in[1];
    const float* ew = (const float*)d_in[2];
    const float* eb = (const float*)d_in[3];
    float* out = (float*)d_out;

    const int full = (out_size >= BB * 2 + BB * EE + 1) ? 1 : 0;

    prep_weights<<<8, 1024>>>(ew);
    moe_fused<<<BB, 256>>>(x, rw, eb, out, full);
    if (full) {
        loss_kernel<<<1, 1024>>>(out + BB * 2 + BB * EE);
    }
}